// round 4
// baseline (speedup 1.0000x reference)
#include <cuda_runtime.h>
#include <cstdint>

#define DDIM 64
#define KCODES 1024
#define NTOK 131072
#define TM 128
#define NTHREADS 256
#define NCHUNKS 16
#define CCHUNK 64
#define CAP 8
#define MARGIN 0.008f

// ---------------- smem layout (bytes) ----------------
#define OFF_XF   0                        // float [128][65]   = 33280
#define OFF_CB   33280                    // tf32  2x[64][68]  = 34816
#define OFF_CN   (33280 + 34816)          // float [1024]      = 4096
#define OFF_CAND (OFF_CN + 4096)          // int   [128][32]   = 16384
#define OFF_XNS  (OFF_CAND + 16384)       // float [128]
#define OFF_WIX  (OFF_XNS + 512)          // int   [128]
#define OFF_OFL  (OFF_WIX + 512)          // int   [128]
#define SMEM_BYTES (OFF_OFL + 512)

__device__ float g_cn[KCODES];   // ||c||^2, sequential mul-then-add (bit-matches ref)

__global__ void vq_prep(const float* __restrict__ cb) {
    int k = blockIdx.x * blockDim.x + threadIdx.x;
    if (k >= KCODES) return;
    float acc = 0.f;
#pragma unroll
    for (int d = 0; d < DDIM; d++) {
        float c = cb[k * DDIM + d];
        acc = __fadd_rn(acc, __fmul_rn(c, c));
    }
    g_cn[k] = acc;
}

__device__ __forceinline__ uint32_t f2tf(float x) {
    uint32_t r;
    asm("cvt.rna.tf32.f32 %0, %1;" : "=r"(r) : "f"(x));
    return r;
}

__device__ __forceinline__ void mma_tf32(float* c, const uint32_t* a,
                                         uint32_t b0, uint32_t b1) {
    asm volatile(
        "mma.sync.aligned.m16n8k8.row.col.f32.tf32.tf32.f32 "
        "{%0,%1,%2,%3}, {%4,%5,%6,%7}, {%8,%9}, {%0,%1,%2,%3};"
        : "+f"(c[0]), "+f"(c[1]), "+f"(c[2]), "+f"(c[3])
        : "r"(a[0]), "r"(a[1]), "r"(a[2]), "r"(a[3]), "r"(b0), "r"(b1));
}

// exact rescore: bit-matches reference (R2-verified formula)
__device__ __forceinline__ float exact_d2(const float* __restrict__ cb,
                                          const float* __restrict__ xrow,
                                          float xn, float cnk, int k) {
    const float4* cr = (const float4*)(cb + k * DDIM);
    float s = 0.f;
#pragma unroll
    for (int i = 0; i < 16; i++) {
        float4 v = cr[i];
        s = __fmaf_rn(xrow[4 * i + 0], v.x, s);
        s = __fmaf_rn(xrow[4 * i + 1], v.y, s);
        s = __fmaf_rn(xrow[4 * i + 2], v.z, s);
        s = __fmaf_rn(xrow[4 * i + 3], v.w, s);
    }
    return __fadd_rn(__fsub_rn(xn, __fmul_rn(2.0f, s)), cnk);
}

__global__ __launch_bounds__(NTHREADS, 2)
void vq_main(const float* __restrict__ h, const float* __restrict__ cb,
             float* __restrict__ outZ, float* __restrict__ outQ) {
    extern __shared__ char smem[];
    float*    Xf   = (float*)(smem + OFF_XF);     // [128][65], exact fp32
    uint32_t* CBu  = (uint32_t*)(smem + OFF_CB);  // tf32 bits, 2 x [64][68]
    float*    Cn   = (float*)(smem + OFF_CN);
    int*      cand = (int*)(smem + OFF_CAND);
    float*    xns  = (float*)(smem + OFF_XNS);
    int*      wix  = (int*)(smem + OFF_WIX);
    int*      ofl  = (int*)(smem + OFF_OFL);

    const int tid = threadIdx.x;
    const int wid = tid >> 5;
    const int lid = tid & 31;
    const int g = lid >> 2;      // groupID (row within m16)
    const int q = lid & 3;       // threadID in group
    const int tw = wid * 16;     // warp's first token (CTA-local)
    const int n0 = blockIdx.x * TM;
    const int b = n0 >> 12;
    const long base = (long)b * 262144 + (n0 & 4095);

    // ---- A fragments: x tile in registers for the whole kernel (tf32) ----
    uint32_t afr[32];
#pragma unroll
    for (int kc = 0; kc < 8; kc++) {
        const float* xp = h + base + (long)(kc * 8 + q) * 4096 + tw + g;
        afr[kc * 4 + 0] = f2tf(xp[0]);
        afr[kc * 4 + 1] = f2tf(xp[8]);            // token row +8
        afr[kc * 4 + 2] = f2tf(xp[4 * 4096]);     // k col +4
        afr[kc * 4 + 3] = f2tf(xp[4 * 4096 + 8]);
    }

    // ---- Xf exact fp32 tile (coalesced d-major load) ----
    for (int i = tid; i < 64 * 32; i += NTHREADS) {
        int d = i >> 5, t4 = i & 31;
        float4 v = *(const float4*)(h + base + (long)d * 4096 + t4 * 4);
        Xf[(t4 * 4 + 0) * 65 + d] = v.x;
        Xf[(t4 * 4 + 1) * 65 + d] = v.y;
        Xf[(t4 * 4 + 2) * 65 + d] = v.z;
        Xf[(t4 * 4 + 3) * 65 + d] = v.w;
    }
    for (int i = tid; i < KCODES; i += NTHREADS) Cn[i] = g_cn[i];
    if (tid < 128) ofl[tid] = 0;

    // ---- preload code chunk 0 ----
    {
        const float* src = cb;  // chunk 0
#pragma unroll
        for (int t = 0; t < 4; t++) {
            int f = tid + t * 256;
            float4 v = *(const float4*)(src + f * 4);
            uint32_t* dst = &CBu[(f >> 4) * 68 + (f & 15) * 4];
            dst[0] = f2tf(v.x); dst[1] = f2tf(v.y);
            dst[2] = f2tf(v.z); dst[3] = f2tf(v.w);
        }
    }
    __syncthreads();

    // ---- exact xn (sequential mul-then-add; replicates reference order) ----
    if (tid < 128) {
        float acc = 0.f;
#pragma unroll
        for (int d = 0; d < 64; d++) {
            float xv = Xf[tid * 65 + d];
            acc = __fadd_rn(acc, __fmul_rn(xv, xv));
        }
        xns[tid] = acc;
    }
    __syncthreads();

    const int tok0 = tw + g, tok1 = tw + g + 8;
    const float xn0 = xns[tok0], xn1 = xns[tok1];
    float best0 = 3.4e38f, best1 = 3.4e38f;
    int cnt0 = 0, cnt1 = 0;

    for (int c = 0; c < NCHUNKS; c++) {
        const uint32_t* CBs = CBu + (c & 1) * (64 * 68 / 4) * 4;  // (c&1)*4352 words
        // prefetch next chunk to regs
        float4 pf[4];
        if (c + 1 < NCHUNKS) {
            const float* src = cb + (c + 1) * (CCHUNK * DDIM);
#pragma unroll
            for (int t = 0; t < 4; t++) pf[t] = *(const float4*)(src + (tid + t * 256) * 4);
        }

        // ---- MMA: 16 tokens x 64 codes x 64 k ----
        float acc[8][4];
#pragma unroll
        for (int j = 0; j < 8; j++)
#pragma unroll
            for (int e = 0; e < 4; e++) acc[j][e] = 0.f;

#pragma unroll
        for (int kc = 0; kc < 8; kc++) {
#pragma unroll
            for (int j = 0; j < 8; j++) {
                uint32_t b0 = CBs[(j * 8 + g) * 68 + kc * 8 + q];
                uint32_t b1 = CBs[(j * 8 + g) * 68 + kc * 8 + q + 4];
                mma_tf32(acc[j], afr + kc * 4, b0, b1);
            }
        }

        // store prefetched chunk (tf32) into other buffer
        if (c + 1 < NCHUNKS) {
            uint32_t* CBd = CBu + ((c + 1) & 1) * 4352;
#pragma unroll
            for (int t = 0; t < 4; t++) {
                int f = tid + t * 256;
                uint32_t* dst = &CBd[(f >> 4) * 68 + (f & 15) * 4];
                dst[0] = f2tf(pf[t].x); dst[1] = f2tf(pf[t].y);
                dst[2] = f2tf(pf[t].z); dst[3] = f2tf(pf[t].w);
            }
        }

        // ---- epilogue: approx d2, candidate collection ----
        const int cbase = c * CCHUNK;
#pragma unroll
        for (int j = 0; j < 8; j++) {
            int k0 = cbase + j * 8 + q * 2;
            float2 cn2 = *(const float2*)&Cn[k0];
            float a00 = xn0 - 2.0f * acc[j][0] + cn2.x;
            float a01 = xn0 - 2.0f * acc[j][1] + cn2.y;
            float a10 = xn1 - 2.0f * acc[j][2] + cn2.x;
            float a11 = xn1 - 2.0f * acc[j][3] + cn2.y;
            if (a00 < best0 + MARGIN) {
                if (cnt0 < CAP) cand[tok0 * 32 + q * 8 + cnt0] = k0; else ofl[tok0] = 1;
                cnt0++; if (a00 < best0) best0 = a00;
            }
            if (a01 < best0 + MARGIN) {
                if (cnt0 < CAP) cand[tok0 * 32 + q * 8 + cnt0] = k0 + 1; else ofl[tok0] = 1;
                cnt0++; if (a01 < best0) best0 = a01;
            }
            if (a10 < best1 + MARGIN) {
                if (cnt1 < CAP) cand[tok1 * 32 + q * 8 + cnt1] = k0; else ofl[tok1] = 1;
                cnt1++; if (a10 < best1) best1 = a10;
            }
            if (a11 < best1 + MARGIN) {
                if (cnt1 < CAP) cand[tok1 * 32 + q * 8 + cnt1] = k0 + 1; else ofl[tok1] = 1;
                cnt1++; if (a11 < best1) best1 = a11;
            }
        }
        // tighten bests across the quad (lanes g*4+q, q=0..3)
#pragma unroll
        for (int off = 1; off < 4; off <<= 1) {
            best0 = fminf(best0, __shfl_xor_sync(0xffffffffu, best0, off));
            best1 = fminf(best1, __shfl_xor_sync(0xffffffffu, best1, off));
        }
        __syncthreads();
    }

    // ---- exact rescore of candidates (bit-matches reference) ----
#pragma unroll
    for (int half = 0; half < 2; half++) {
        int t = half ? tok1 : tok0;
        int cnt = half ? cnt1 : cnt0;
        const float* xrow = &Xf[t * 65];
        float xn = half ? xn1 : xn0;
        float bv = 3.4e38f;
        int bi = 0x7fffffff;
        if (ofl[t]) {
            // cooperative exact full scan (rare): lane q takes k = q, q+4, ...
            for (int k = q; k < KCODES; k += 4) {
                float d2 = exact_d2(cb, xrow, xn, Cn[k], k);
                if (d2 < bv || (d2 == bv && k < bi)) { bv = d2; bi = k; }
            }
        } else {
            for (int i = 0; i < cnt; i++) {
                int k = cand[t * 32 + q * 8 + i];
                float d2 = exact_d2(cb, xrow, xn, Cn[k], k);
                if (d2 < bv || (d2 == bv && k < bi)) { bv = d2; bi = k; }
            }
        }
#pragma unroll
        for (int off = 1; off < 4; off <<= 1) {
            float ov = __shfl_xor_sync(0xffffffffu, bv, off);
            int oi = __shfl_xor_sync(0xffffffffu, bi, off);
            if (ov < bv || (ov == bv && oi < bi)) { bv = ov; bi = oi; }
        }
        if (q == 0) {
            wix[t] = bi;
            if (outZ) outZ[n0 + t] = (float)bi;
        }
    }
    __syncthreads();

    // ---- q gather ----
    if (outQ) {
        for (int i = tid; i < 128 * 16; i += NTHREADS) {
            int tt = i >> 4, c4 = i & 15;
            float4 v = *(const float4*)&cb[wix[tt] * DDIM + c4 * 4];
            *(float4*)&outQ[(long)(n0 + tt) * DDIM + c4 * 4] = v;
        }
    }
}

extern "C" void kernel_launch(void* const* d_in, const int* in_sizes, int n_in,
                              void* d_out, int out_size) {
    const float* h = (const float*)d_in[0];
    const float* cb = (const float*)d_in[1];
    float* out = (float*)d_out;

    float* outZ = nullptr;
    float* outQ = nullptr;
    if (out_size >= NTOK + NTOK * DDIM) { outZ = out; outQ = out + NTOK; }
    else if (out_size == NTOK * DDIM)   { outQ = out; }
    else                                { outZ = out; }

    cudaFuncSetAttribute(vq_main, cudaFuncAttributeMaxDynamicSharedMemorySize, SMEM_BYTES);
    vq_prep<<<(KCODES + 255) / 256, 256>>>(cb);
    vq_main<<<NTOK / TM, NTHREADS, SMEM_BYTES>>>(h, cb, outZ, outQ);
}